// round 5
// baseline (speedup 1.0000x reference)
#include <cuda_runtime.h>
#include <cuda_bf16.h>
#include <cstdint>
#include <cstddef>

#define B_  32
#define T_  1024
#define D_  512
#define H_  512
#define G4H 2048
#define GB  4        // batch groups (8 batches each)
#define GU  32       // unit groups (16 units each)
#define GRID_REC (GB * GU)
#define TPB_REC  512

// ---------------- scratch (device globals: no allocation allowed) -------------
__device__ __align__(16) float g_xz[(size_t)T_ * B_ * G4H]; // [t][b][4H]
__device__ __align__(16) float g_hf[2][GB][512 * 8];        // [buf][grp][unit(512)][b(8)]
__device__ unsigned g_bar4[GB * 32];                         // 1 counter / 128B line
__device__ unsigned g_exit4[GB * 32];

// ---------------- helpers ----------------------------------------------------
union F2U { float2 f; unsigned long long u; };

__device__ __forceinline__ void ffma2(float2& d, float2 a, float2 b) {
    F2U D, A, Bv; D.f = d; A.f = a; Bv.f = b;
    asm("fma.rn.f32x2 %0, %1, %2, %0;" : "+l"(D.u) : "l"(A.u), "l"(Bv.u));
    d = D.f;
}
__device__ __forceinline__ float sigf(float x) {
    return __fdividef(1.f, 1.f + __expf(-x));
}
__device__ __forceinline__ float tanf_(float x) {
    return 2.f * sigf(2.f * x) - 1.f;
}
__device__ __forceinline__ float2 sig2(float2 v) { return make_float2(sigf(v.x), sigf(v.y)); }
__device__ __forceinline__ float2 th2(float2 v)  { return make_float2(tanf_(v.x), tanf_(v.y)); }

// lengths dtype robustness: JAX x64-off makes "int64" silently int32. Detect
// using only the first 128 bytes: all 16 odd int32 slots zero => real int64.
__device__ __forceinline__ int read_length(const int* L32, int b) {
    bool is64 = true;
    #pragma unroll
    for (int i = 1; i < 32; i += 2) is64 &= (L32[i] == 0);
    return is64 ? L32[2 * b] : L32[b];
}

// ---------------- kernel 1: xz = X @ Wx + bias --------------------------------
// M=32768 (m = t*32+b), N=2048, K=512. 128x128 tile, 8x8/thread, reg prefetch.
__global__ void __launch_bounds__(256, 2) gemm_xw_kernel(
    const float* __restrict__ X,
    const float* __restrict__ Wx,
    const float* __restrict__ bias)
{
    __shared__ __align__(16) float2 ash[16][128];  // A dup (a,a)  [kk][row]
    __shared__ __align__(16) float2 bsh[16][64];   // B col-pairs  [kk][npair]

    const int tid = threadIdx.x;
    const int n0 = blockIdx.x * 128;
    const int m0 = blockIdx.y * 128;
    const int rg = tid >> 4, cg = tid & 15;
    const int r0 = rg * 8, np0 = cg * 4;

    int qa0 = tid, qa1 = tid + 256;
    int rowA0 = qa0 >> 2, kkA0 = (qa0 & 3) * 4;
    int rowA1 = qa1 >> 2, kkA1 = (qa1 & 3) * 4;
    int mA0 = m0 + rowA0, tA0 = mA0 >> 5, bA0 = mA0 & 31;
    int mA1 = m0 + rowA1, tA1 = mA1 >> 5, bA1 = mA1 & 31;
    const float* pA0 = X + ((size_t)bA0 * T_ + tA0) * D_ + kkA0;
    const float* pA1 = X + ((size_t)bA1 * T_ + tA1) * D_ + kkA1;
    int kkB0 = qa0 >> 5, nnB0 = (qa0 & 31) * 4;
    int kkB1 = qa1 >> 5, nnB1 = (qa1 & 31) * 4;
    const float* pB0 = Wx + (size_t)kkB0 * G4H + n0 + nnB0;
    const float* pB1 = Wx + (size_t)kkB1 * G4H + n0 + nnB1;

    float2 acc[8][4];
    #pragma unroll
    for (int r = 0; r < 8; r++)
        #pragma unroll
        for (int c = 0; c < 4; c++) acc[r][c] = make_float2(0.f, 0.f);

    float4 ra0 = *(const float4*)pA0;
    float4 ra1 = *(const float4*)pA1;
    float4 rb0 = *(const float4*)pB0;
    float4 rb1 = *(const float4*)pB1;

    for (int k0 = 0; k0 < D_; k0 += 16) {
        ash[kkA0 + 0][rowA0] = make_float2(ra0.x, ra0.x);
        ash[kkA0 + 1][rowA0] = make_float2(ra0.y, ra0.y);
        ash[kkA0 + 2][rowA0] = make_float2(ra0.z, ra0.z);
        ash[kkA0 + 3][rowA0] = make_float2(ra0.w, ra0.w);
        ash[kkA1 + 0][rowA1] = make_float2(ra1.x, ra1.x);
        ash[kkA1 + 1][rowA1] = make_float2(ra1.y, ra1.y);
        ash[kkA1 + 2][rowA1] = make_float2(ra1.z, ra1.z);
        ash[kkA1 + 3][rowA1] = make_float2(ra1.w, ra1.w);
        bsh[kkB0][(nnB0 >> 1) + 0] = make_float2(rb0.x, rb0.y);
        bsh[kkB0][(nnB0 >> 1) + 1] = make_float2(rb0.z, rb0.w);
        bsh[kkB1][(nnB1 >> 1) + 0] = make_float2(rb1.x, rb1.y);
        bsh[kkB1][(nnB1 >> 1) + 1] = make_float2(rb1.z, rb1.w);
        __syncthreads();

        if (k0 + 16 < D_) {
            ra0 = *(const float4*)(pA0 + k0 + 16);
            ra1 = *(const float4*)(pA1 + k0 + 16);
            rb0 = *(const float4*)(pB0 + (size_t)(k0 + 16) * G4H);
            rb1 = *(const float4*)(pB1 + (size_t)(k0 + 16) * G4H);
        }

        #pragma unroll
        for (int kk = 0; kk < 16; kk++) {
            float2 a[8], bb[4];
            #pragma unroll
            for (int i = 0; i < 4; i++) {
                float4 v = *(const float4*)&ash[kk][r0 + i * 2];
                a[i * 2 + 0] = make_float2(v.x, v.y);
                a[i * 2 + 1] = make_float2(v.z, v.w);
            }
            #pragma unroll
            for (int i = 0; i < 2; i++) {
                float4 v = *(const float4*)&bsh[kk][np0 + i * 2];
                bb[i * 2 + 0] = make_float2(v.x, v.y);
                bb[i * 2 + 1] = make_float2(v.z, v.w);
            }
            #pragma unroll
            for (int r = 0; r < 8; r++)
                #pragma unroll
                for (int c = 0; c < 4; c++)
                    ffma2(acc[r][c], a[r], bb[c]);
        }
        __syncthreads();
    }

    #pragma unroll
    for (int r = 0; r < 8; r++) {
        int m = m0 + r0 + r;
        #pragma unroll
        for (int c = 0; c < 4; c++) {
            int n = n0 + (np0 + c) * 2;
            float2 bv = *(const float2*)(bias + n);
            float2 o = make_float2(acc[r][c].x + bv.x, acc[r][c].y + bv.y);
            *(float2*)(g_xz + (size_t)m * G4H + n) = o;
        }
    }
}

// ---------------- kernel 2: persistent recurrence -----------------------------
// Grid 128 = 4 batch-groups x 32 unit-groups; 512 threads (16 warps).
// CTA (gb,gu): batches 8gb..+7, units 16gu..+15 (64 cols = 32 col-pairs).
// SMEM:
//   wsh[512 d][32 cp] float2 = (w_even, w_odd)            128KB
//   hsh[512 d][8 b]   float2 = (h_b, h_b) duplicated       32KB
//   zsh[16 ks][32 cp][10 b-slot] float2 partials (pad!)    40KB
//   csh[8 up][8 b]    float2 c-state                       512B
// Thread (cpq 0..7, bq 0..3, ks = tid>>5 warp-uniform): 4 cp x 2 b x 32 d.
#define ZP 10   // padded b-pitch of zsh (float2 units)
__global__ void __launch_bounds__(TPB_REC) lstm_rec_kernel(
    const float* __restrict__ Wh,
    const int* __restrict__ lengths_raw,
    float* __restrict__ out)
{
    extern __shared__ __align__(16) char smem[];
    float2* wsh = (float2*)smem;                       // 512*32
    float2* hsh = (float2*)(smem + 131072);            // 512*8
    float2* zsh = (float2*)(smem + 131072 + 32768);    // 16*32*ZP
    float2* csh = (float2*)(smem + 131072 + 32768 + 16 * 32 * ZP * 8);

    const int tid = threadIdx.x;
    const int gb = blockIdx.x >> 5;        // batch group 0..3
    const int gu = blockIdx.x & 31;        // unit group 0..31
    const int u0 = gu * 16;
    const int b0 = gb * 8;

    // Preload Wh as col-pairs: wsh[d][cp], cp = gate*8 + up.
    for (int idx = tid; idx < 512 * 32; idx += TPB_REC) {
        int d = idx >> 5, cp = idx & 31;
        int gate = cp >> 3, up = cp & 7;
        wsh[idx] = *(const float2*)(Wh + (size_t)d * G4H + gate * H_ + u0 + 2 * up);
    }
    if (tid < 64) csh[tid] = make_float2(0.f, 0.f);
    __syncthreads();

    const int cpq = tid & 7;
    const int bq  = (tid >> 3) & 3;
    const int ks  = tid >> 5;              // 0..15, warp-uniform, 32 d each
    const int dbase = ks * 32;
    const float4* wf = ((const float4*)wsh) + (size_t)dbase * 16 + cpq * 2;
    const float4* hf = ((const float4*)hsh) + (size_t)dbase * 4 + bq;

    const int up_g = tid >> 3;             // gate-phase unit-pair (tid < 64)
    const int b_g  = tid & 7;              // gate-phase batch

    unsigned* bar = &g_bar4[gb * 32];

    // prefetch xz for t=0
    float2 xz2[4];
    if (tid < 64) {
        const float* base = g_xz + ((size_t)b0 + b_g) * G4H + u0 + 2 * up_g;
        #pragma unroll
        for (int g = 0; g < 4; g++)
            xz2[g] = *(const float2*)(base + (size_t)g * H_);
    }

    for (int t = 0; t < T_; t++) {
        const int rb = t & 1, wb = rb ^ 1;

        float2 acc[4][2];
        #pragma unroll
        for (int j = 0; j < 4; j++) {
            acc[j][0] = make_float2(0.f, 0.f);
            acc[j][1] = make_float2(0.f, 0.f);
        }

        if (t > 0) {
            // stage 16KB of h for this batch group (L2, duplicate on the fly)
            const float4* src = (const float4*)(g_hf[rb][gb]);
            #pragma unroll
            for (int i = 0; i < 2; i++) {
                int idx = tid + i * TPB_REC;      // 0..1023 float4 slots
                int d = idx >> 1, half = idx & 1;
                float4 v = __ldcg(src + idx);
                float4* dst = (float4*)hsh + (size_t)d * 4 + half * 2;
                dst[0] = make_float4(v.x, v.x, v.y, v.y);
                dst[1] = make_float4(v.z, v.z, v.w, v.w);
            }
            __syncthreads();

            #pragma unroll 4
            for (int dd = 0; dd < 32; dd++) {
                float4 wA = wf[dd * 16], wB = wf[dd * 16 + 1];
                float4 hA = hf[dd * 4];
                float2 w0 = make_float2(wA.x, wA.y), w1 = make_float2(wA.z, wA.w);
                float2 w2 = make_float2(wB.x, wB.y), w3 = make_float2(wB.z, wB.w);
                float2 h0 = make_float2(hA.x, hA.y), h1 = make_float2(hA.z, hA.w);
                ffma2(acc[0][0], h0, w0); ffma2(acc[0][1], h1, w0);
                ffma2(acc[1][0], h0, w1); ffma2(acc[1][1], h1, w1);
                ffma2(acc[2][0], h0, w2); ffma2(acc[2][1], h1, w2);
                ffma2(acc[3][0], h0, w3); ffma2(acc[3][1], h1, w3);
            }
        }

        // write partials: zsh[ks][cp][b-slot], float4 = 2 batches (bq*2, +1)
        #pragma unroll
        for (int j = 0; j < 4; j++) {
            float2* zp = zsh + (size_t)ks * (32 * ZP) + (cpq * 4 + j) * ZP + bq * 2;
            *(float4*)zp = make_float4(acc[j][0].x, acc[j][0].y,
                                       acc[j][1].x, acc[j][1].y);
        }
        __syncthreads();

        // gates: 64 threads = 8 unit-pairs x 8 batches; float2 = 2 units
        if (tid < 64) {
            float2 z[4];
            #pragma unroll
            for (int g = 0; g < 4; g++) {
                float2 s = xz2[g];
                int cp = g * 8 + up_g;
                #pragma unroll
                for (int k = 0; k < 16; k++) {
                    float2 v = zsh[k * (32 * ZP) + cp * ZP + b_g];
                    s.x += v.x; s.y += v.y;
                }
                z[g] = s;
            }
            float2 ig = sig2(z[0]);
            float2 fg = sig2(z[1]);
            float2 gg = th2(z[2]);
            float2 og = sig2(z[3]);
            float2 cold = csh[up_g * 8 + b_g];
            float2 nc = make_float2(fg.x * cold.x + ig.x * gg.x,
                                    fg.y * cold.y + ig.y * gg.y);
            float2 tc = th2(nc);
            float2 nh = make_float2(og.x * tc.x, og.y * tc.y);
            csh[up_g * 8 + b_g] = nc;

            int u = u0 + 2 * up_g;
            float* hb = g_hf[wb][gb];
            hb[(u + 0) * 8 + b_g] = nh.x;
            hb[(u + 1) * 8 + b_g] = nh.y;
            *(float2*)(out + ((size_t)(b0 + b_g) * T_ + t) * H_ + u) = nh;
            __threadfence();
        }
        __syncthreads();

        // barrier arrive, then prefetch xz(t+1) so its latency hides in the wait
        if (tid == 0) atomicAdd(bar, 1u);
        if (tid < 64 && t + 1 < T_) {
            const float* base = g_xz + ((size_t)(t + 1) * B_ + b0 + b_g) * G4H
                              + u0 + 2 * up_g;
            #pragma unroll
            for (int g = 0; g < 4; g++)
                xz2[g] = *(const float2*)(base + (size_t)g * H_);
        }
        if (tid == 0) {
            unsigned target = (unsigned)(t + 1) * 32u;
            while (*((volatile unsigned*)bar) < target) { }
        }
        __syncthreads();
    }

    // final states: this CTA owns (b0..b0+7) x (u0..u0+15)
    for (int idx = tid; idx < 128; idx += TPB_REC) {
        int b = b0 + (idx >> 4), u = u0 + (idx & 15);
        int len = read_length(lengths_raw, b);
        int lt = len > 0 ? len - 1 : 0;
        if (lt > T_ - 1) lt = T_ - 1;
        out[(size_t)B_ * T_ * H_ + (size_t)b * H_ + u] =
            out[((size_t)b * T_ + (size_t)lt) * H_ + u];
    }
    __syncthreads();

    // reset this group's counters for the next graph replay
    if (tid == 0) {
        unsigned ticket = atomicAdd(&g_exit4[gb * 32], 1u);
        if (ticket == 31u) {
            g_bar4[gb * 32] = 0;
            g_exit4[gb * 32] = 0;
            __threadfence();
        }
    }
}

// ---------------- launch ------------------------------------------------------
extern "C" void kernel_launch(void* const* d_in, const int* in_sizes, int n_in,
                              void* d_out, int out_size)
{
    const float* X       = (const float*)d_in[0];
    const int*   lengths = (const int*)d_in[1];   // int32/int64 autodetected
    const float* Wx      = (const float*)d_in[2];
    const float* Wh      = (const float*)d_in[3];
    const float* bias    = (const float*)d_in[4];
    float*       out     = (float*)d_out;

    dim3 g1(G4H / 128, (B_ * T_) / 128);
    gemm_xw_kernel<<<g1, 256>>>(X, Wx, bias);

    static const size_t SMEM_REC = 131072 + 32768 + 16 * 32 * ZP * 8 + 512; // 205,312 B
    cudaFuncSetAttribute(lstm_rec_kernel,
                         cudaFuncAttributeMaxDynamicSharedMemorySize, (int)SMEM_REC);
    lstm_rec_kernel<<<GRID_REC, TPB_REC, SMEM_REC>>>(Wh, lengths, out);
}

// round 8
// speedup vs baseline: 1.0266x; 1.0266x over previous
#include <cuda_runtime.h>
#include <cuda_bf16.h>
#include <cstdint>
#include <cstddef>

#define B_  32
#define T_  1024
#define D_  512
#define H_  512
#define G4H 2048
#define GB  4        // batch groups (8 batches each)
#define GU  32       // unit groups (16 units each)
#define GRID_REC (GB * GU)
#define TPB_REC  256
#define KS  8        // k-split groups (one per warp)
#define DPK 64       // d per ks
#define ZP  10       // padded b-pitch of zsh (float2 units)

// ---------------- scratch (device globals: no allocation allowed) -------------
__device__ __align__(16) float g_xz[(size_t)T_ * B_ * G4H]; // [t][b][4H]
__device__ __align__(16) float g_hf[2][GB][512 * 8];        // [buf][grp][unit][b(8)]
__device__ __align__(128) unsigned g_bar4[GB * 32];         // 1 counter / line per group
__device__ unsigned g_exit4[GB * 32];

// ---------------- helpers ----------------------------------------------------
union F2U { float2 f; unsigned long long u; };

__device__ __forceinline__ void ffma2(float2& d, float2 a, float2 b) {
    F2U D, A, Bv; D.f = d; A.f = a; Bv.f = b;
    asm("fma.rn.f32x2 %0, %1, %2, %0;" : "+l"(D.u) : "l"(A.u), "l"(Bv.u));
    d = D.f;
}
__device__ __forceinline__ float sigf(float x) {
    return __fdividef(1.f, 1.f + __expf(-x));
}
__device__ __forceinline__ float tanf_(float x) {
    return 2.f * sigf(2.f * x) - 1.f;
}
__device__ __forceinline__ float2 sig2(float2 v) { return make_float2(sigf(v.x), sigf(v.y)); }
__device__ __forceinline__ float2 th2(float2 v)  { return make_float2(tanf_(v.x), tanf_(v.y)); }

__device__ __forceinline__ void cp_async16(void* dst, const void* src) {
    unsigned ds = (unsigned)__cvta_generic_to_shared(dst);
    asm volatile("cp.async.cg.shared.global [%0], [%1], 16;" :: "r"(ds), "l"(src) : "memory");
}

// lengths dtype robustness: JAX x64-off makes "int64" silently int32. Detect
// using only the first 128 bytes: all 16 odd int32 slots zero => real int64.
__device__ __forceinline__ int read_length(const int* L32, int b) {
    bool is64 = true;
    #pragma unroll
    for (int i = 1; i < 32; i += 2) is64 &= (L32[i] == 0);
    return is64 ? L32[2 * b] : L32[b];
}

// ---------------- kernel 1: xz = X @ Wx + bias --------------------------------
// M=32768 (m = t*32+b), N=2048, K=512. 128x128 tile, 8x8/thread, reg prefetch.
__global__ void __launch_bounds__(256, 2) gemm_xw_kernel(
    const float* __restrict__ X,
    const float* __restrict__ Wx,
    const float* __restrict__ bias)
{
    __shared__ __align__(16) float2 ash[16][128];  // A dup (a,a)  [kk][row]
    __shared__ __align__(16) float2 bsh[16][64];   // B col-pairs  [kk][npair]

    const int tid = threadIdx.x;
    const int n0 = blockIdx.x * 128;
    const int m0 = blockIdx.y * 128;
    const int rg = tid >> 4, cg = tid & 15;
    const int r0 = rg * 8, np0 = cg * 4;

    int qa0 = tid, qa1 = tid + 256;
    int rowA0 = qa0 >> 2, kkA0 = (qa0 & 3) * 4;
    int rowA1 = qa1 >> 2, kkA1 = (qa1 & 3) * 4;
    int mA0 = m0 + rowA0, tA0 = mA0 >> 5, bA0 = mA0 & 31;
    int mA1 = m0 + rowA1, tA1 = mA1 >> 5, bA1 = mA1 & 31;
    const float* pA0 = X + ((size_t)bA0 * T_ + tA0) * D_ + kkA0;
    const float* pA1 = X + ((size_t)bA1 * T_ + tA1) * D_ + kkA1;
    int kkB0 = qa0 >> 5, nnB0 = (qa0 & 31) * 4;
    int kkB1 = qa1 >> 5, nnB1 = (qa1 & 31) * 4;
    const float* pB0 = Wx + (size_t)kkB0 * G4H + n0 + nnB0;
    const float* pB1 = Wx + (size_t)kkB1 * G4H + n0 + nnB1;

    float2 acc[8][4];
    #pragma unroll
    for (int r = 0; r < 8; r++)
        #pragma unroll
        for (int c = 0; c < 4; c++) acc[r][c] = make_float2(0.f, 0.f);

    float4 ra0 = *(const float4*)pA0;
    float4 ra1 = *(const float4*)pA1;
    float4 rb0 = *(const float4*)pB0;
    float4 rb1 = *(const float4*)pB1;

    for (int k0 = 0; k0 < D_; k0 += 16) {
        ash[kkA0 + 0][rowA0] = make_float2(ra0.x, ra0.x);
        ash[kkA0 + 1][rowA0] = make_float2(ra0.y, ra0.y);
        ash[kkA0 + 2][rowA0] = make_float2(ra0.z, ra0.z);
        ash[kkA0 + 3][rowA0] = make_float2(ra0.w, ra0.w);
        ash[kkA1 + 0][rowA1] = make_float2(ra1.x, ra1.x);
        ash[kkA1 + 1][rowA1] = make_float2(ra1.y, ra1.y);
        ash[kkA1 + 2][rowA1] = make_float2(ra1.z, ra1.z);
        ash[kkA1 + 3][rowA1] = make_float2(ra1.w, ra1.w);
        bsh[kkB0][(nnB0 >> 1) + 0] = make_float2(rb0.x, rb0.y);
        bsh[kkB0][(nnB0 >> 1) + 1] = make_float2(rb0.z, rb0.w);
        bsh[kkB1][(nnB1 >> 1) + 0] = make_float2(rb1.x, rb1.y);
        bsh[kkB1][(nnB1 >> 1) + 1] = make_float2(rb1.z, rb1.w);
        __syncthreads();

        if (k0 + 16 < D_) {
            ra0 = *(const float4*)(pA0 + k0 + 16);
            ra1 = *(const float4*)(pA1 + k0 + 16);
            rb0 = *(const float4*)(pB0 + (size_t)(k0 + 16) * G4H);
            rb1 = *(const float4*)(pB1 + (size_t)(k0 + 16) * G4H);
        }

        #pragma unroll
        for (int kk = 0; kk < 16; kk++) {
            float2 a[8], bb[4];
            #pragma unroll
            for (int i = 0; i < 4; i++) {
                float4 v = *(const float4*)&ash[kk][r0 + i * 2];
                a[i * 2 + 0] = make_float2(v.x, v.y);
                a[i * 2 + 1] = make_float2(v.z, v.w);
            }
            #pragma unroll
            for (int i = 0; i < 2; i++) {
                float4 v = *(const float4*)&bsh[kk][np0 + i * 2];
                bb[i * 2 + 0] = make_float2(v.x, v.y);
                bb[i * 2 + 1] = make_float2(v.z, v.w);
            }
            #pragma unroll
            for (int r = 0; r < 8; r++)
                #pragma unroll
                for (int c = 0; c < 4; c++)
                    ffma2(acc[r][c], a[r], bb[c]);
        }
        __syncthreads();
    }

    #pragma unroll
    for (int r = 0; r < 8; r++) {
        int m = m0 + r0 + r;
        #pragma unroll
        for (int c = 0; c < 4; c++) {
            int n = n0 + (np0 + c) * 2;
            float2 bv = *(const float2*)(bias + n);
            float2 o = make_float2(acc[r][c].x + bv.x, acc[r][c].y + bv.y);
            *(float2*)(g_xz + (size_t)m * G4H + n) = o;
        }
    }
}

// ---------------- kernel 2: persistent recurrence -----------------------------
// Grid 128 = 4 batch-groups x 32 unit-groups; 256 threads (8 warps).
// CTA (gb,gu): batches 8gb..+7, units 16gu..+15 (64 cols = 32 col-pairs).
// SMEM:
//   wsh[512 d][32 cp] float2 = (w_even, w_odd)            128 KB
//   hsh[512 d][8 b]   float  (NOT duplicated)              16 KB
//   zsh[8 ks][32 cp][ZP] float2 partials                   20 KB
//   csh[8 up][8 b]    float2 c-state                       512 B
//   xzsh[2][8 b][4 g][16 u] float (double-buffered xz)      4 KB
// Thread (cpq=tid&7, bq=(tid>>3)&3, ks=tid>>5): 4 cp x 2 b x 64 d.
#define SM_W   0
#define SM_H   131072
#define SM_Z   (131072 + 16384)
#define SM_C   (SM_Z + KS * 32 * ZP * 8)
#define SM_XZ  (SM_C + 512)
#define SM_TOT (SM_XZ + 4096)
__global__ void __launch_bounds__(TPB_REC) lstm_rec_kernel(
    const float* __restrict__ Wh,
    const int* __restrict__ lengths_raw,
    float* __restrict__ out)
{
    extern __shared__ __align__(16) char smem[];
    float2* wsh  = (float2*)(smem + SM_W);
    float*  hsh  = (float*)(smem + SM_H);
    float2* zsh  = (float2*)(smem + SM_Z);
    float2* csh  = (float2*)(smem + SM_C);
    float*  xzsh = (float*)(smem + SM_XZ);

    const int tid = threadIdx.x;
    const int gb = blockIdx.x >> 5;        // batch group 0..3
    const int gu = blockIdx.x & 31;        // unit group 0..31
    const int u0 = gu * 16;
    const int b0 = gb * 8;

    // Preload Wh as col-pairs: wsh[d][cp], cp = gate*8 + up.
    for (int idx = tid; idx < 512 * 32; idx += TPB_REC) {
        int d = idx >> 5, cp = idx & 31;
        int gate = cp >> 3, up = cp & 7;
        wsh[idx] = *(const float2*)(Wh + (size_t)d * G4H + gate * H_ + u0 + 2 * up);
    }
    if (tid < 64) csh[tid] = make_float2(0.f, 0.f);
    // prestage xz(0) into buffer 0
    if (tid < 128) {
        int b = tid >> 4, gate = (tid >> 2) & 3, q = tid & 3;
        float4 v = __ldg((const float4*)(g_xz + ((size_t)(b0 + b)) * G4H
                                         + gate * H_ + u0 + q * 4));
        *(float4*)(xzsh + b * 64 + gate * 16 + q * 4) = v;
    }
    __syncthreads();

    const int cpq = tid & 7;
    const int bq  = (tid >> 3) & 3;
    const int ks  = tid >> 5;              // warp-uniform, 64 d each
    const int dbase = ks * DPK;
    const float4* wf = ((const float4*)wsh) + (size_t)dbase * 16 + cpq * 2;
    const float2* hp = ((const float2*)hsh) + (size_t)dbase * 4 + bq;

    const int up_g = tid >> 3;             // gate-phase unit-pair (tid < 64)
    const int b_g  = tid & 7;              // gate-phase batch

    unsigned* bar = &g_bar4[gb * 32];

    for (int t = 0; t < T_; t++) {
        const int rb = t & 1, wb = rb ^ 1;

        float2 acc[4][2];
        #pragma unroll
        for (int j = 0; j < 4; j++) {
            acc[j][0] = make_float2(0.f, 0.f);
            acc[j][1] = make_float2(0.f, 0.f);
        }

        if (t > 0) {
            // bulk-stage 16KB of h straight to SMEM via cp.async (L2-coherent)
            const char* src = (const char*)(g_hf[rb][gb]);
            #pragma unroll
            for (int i = 0; i < 4; i++) {
                int off = (tid + i * TPB_REC) * 16;
                cp_async16((char*)hsh + off, src + off);
            }
            asm volatile("cp.async.wait_all;" ::: "memory");
            __syncthreads();                                    // sync A

            #pragma unroll 8
            for (int d = 0; d < DPK; d++) {
                float4 wA = wf[d * 16], wB = wf[d * 16 + 1];
                float2 h2 = hp[d * 4];
                float2 h0 = make_float2(h2.x, h2.x);
                float2 h1 = make_float2(h2.y, h2.y);
                float2 w0 = make_float2(wA.x, wA.y), w1 = make_float2(wA.z, wA.w);
                float2 w2 = make_float2(wB.x, wB.y), w3 = make_float2(wB.z, wB.w);
                ffma2(acc[0][0], h0, w0); ffma2(acc[0][1], h1, w0);
                ffma2(acc[1][0], h0, w1); ffma2(acc[1][1], h1, w1);
                ffma2(acc[2][0], h0, w2); ffma2(acc[2][1], h1, w2);
                ffma2(acc[3][0], h0, w3); ffma2(acc[3][1], h1, w3);
            }
        }

        // write partials: zsh[ks][cp][b-slot]; float4 = 2 batches (bq*2, +1)
        #pragma unroll
        for (int j = 0; j < 4; j++) {
            float2* zp = zsh + (size_t)ks * (32 * ZP) + (cpq * 4 + j) * ZP + bq * 2;
            *(float4*)zp = make_float4(acc[j][0].x, acc[j][0].y,
                                       acc[j][1].x, acc[j][1].y);
        }
        __syncthreads();                                        // sync B

        if (tid < 64) {
            // gates: 8 unit-pairs x 8 batches; float2 = 2 units
            const float* xzb = xzsh + (t & 1) * 512 + b_g * 64;
            float2 z[4];
            #pragma unroll
            for (int g = 0; g < 4; g++) {
                float2 s = *(const float2*)(xzb + g * 16 + 2 * up_g);
                int cp = g * 8 + up_g;
                #pragma unroll
                for (int k = 0; k < KS; k++) {
                    float2 v = zsh[k * (32 * ZP) + cp * ZP + b_g];
                    s.x += v.x; s.y += v.y;
                }
                z[g] = s;
            }
            float2 ig = sig2(z[0]);
            float2 fg = sig2(z[1]);
            float2 gg = th2(z[2]);
            float2 og = sig2(z[3]);
            float2 cold = csh[up_g * 8 + b_g];
            float2 nc = make_float2(fg.x * cold.x + ig.x * gg.x,
                                    fg.y * cold.y + ig.y * gg.y);
            float2 tc = th2(nc);
            float2 nh = make_float2(og.x * tc.x, og.y * tc.y);
            csh[up_g * 8 + b_g] = nc;

            int u = u0 + 2 * up_g;
            float* hb = g_hf[wb][gb];
            hb[(u + 0) * 8 + b_g] = nh.x;
            hb[(u + 1) * 8 + b_g] = nh.y;
            *(float2*)(out + ((size_t)(b0 + b_g) * T_ + t) * H_ + u) = nh;
        } else if (tid >= 128 && t + 1 < T_) {
            // stage xz(t+1) into the other buffer (hidden under gate phase)
            int j = tid - 128;
            int b = j >> 4, gate = (j >> 2) & 3, q = j & 3;
            float4 v = __ldg((const float4*)(g_xz
                         + ((size_t)(t + 1) * B_ + b0 + b) * G4H
                         + gate * H_ + u0 + q * 4));
            *(float4*)(xzsh + ((t + 1) & 1) * 512 + b * 64 + gate * 16 + q * 4) = v;
        }
        __syncthreads();                                        // sync C

        // per-group barrier (32 CTAs, monotonic atomic counter; R4-proven)
        if (tid == 0) {
            __threadfence();                 // release all CTA stores (cumulative)
            atomicAdd(bar, 1u);
            unsigned target = (unsigned)(t + 1) * 32u;
            while (*((volatile unsigned*)bar) < target) { }
            __threadfence();                 // acquire
        }
        __syncthreads();                                        // sync D
    }

    // final states: this CTA owns (b0..b0+7) x (u0..u0+15)
    for (int idx = tid; idx < 128; idx += TPB_REC) {
        int b = b0 + (idx >> 4), u = u0 + (idx & 15);
        int len = read_length(lengths_raw, b);
        int lt = len > 0 ? len - 1 : 0;
        if (lt > T_ - 1) lt = T_ - 1;
        out[(size_t)B_ * T_ * H_ + (size_t)b * H_ + u] =
            out[((size_t)b * T_ + (size_t)lt) * H_ + u];
    }
    __syncthreads();

    // reset this group's counters for the next graph replay (last exiter)
    if (tid == 0) {
        unsigned ticket = atomicAdd(&g_exit4[gb * 32], 1u);
        if (ticket == 31u) {
            g_bar4[gb * 32] = 0;
            g_exit4[gb * 32] = 0;
            __threadfence();
        }
    }
}

// ---------------- launch ------------------------------------------------------
extern "C" void kernel_launch(void* const* d_in, const int* in_sizes, int n_in,
                              void* d_out, int out_size)
{
    const float* X       = (const float*)d_in[0];
    const int*   lengths = (const int*)d_in[1];   // int32/int64 autodetected
    const float* Wx      = (const float*)d_in[2];
    const float* Wh      = (const float*)d_in[3];
    const float* bias    = (const float*)d_in[4];
    float*       out     = (float*)d_out;

    dim3 g1(G4H / 128, (B_ * T_) / 128);
    gemm_xw_kernel<<<g1, 256>>>(X, Wx, bias);

    cudaFuncSetAttribute(lstm_rec_kernel,
                         cudaFuncAttributeMaxDynamicSharedMemorySize, SM_TOT);
    lstm_rec_kernel<<<GRID_REC, TPB_REC, SM_TOT>>>(Wh, lengths, out);
}